// round 9
// baseline (speedup 1.0000x reference)
#include <cuda_runtime.h>
#include <cstdint>

#define NNODES 100000
#define NEDGES 1600000
#define FIN  128
#define FHID 128
#define FOUT 64

// Scratch (allocation-free rule: __device__ globals)
__device__ float g_dinv[NNODES];
__device__ int   g_deg [NNODES];
__device__ int   g_rowptr[NNODES];
__device__ int   g_cursor[NNODES];
__device__ int   g_adj [NEDGES];
__device__ int   g_blockSums[256];
__device__ float g_G  [NNODES * FHID];   // pre-scaled GEMM output (dinv[v]*h_v)
__device__ float g_ACC[NNODES * FHID];   // aggregated output / next-layer input

__device__ __forceinline__ uint32_t smem_u32(const void* p) {
    uint32_t a;
    asm("{ .reg .u64 t; cvta.to.shared.u64 t, %1; cvt.u32.u64 %0, t; }" : "=r"(a) : "l"(p));
    return a;
}

// ---------------- degree / norm / CSR build ----------------

__global__ void deg_count(const int* __restrict__ dst, int* deg, int e) {
    int i = blockIdx.x * blockDim.x + threadIdx.x;
    if (i < e) atomicAdd(&deg[dst[i]], 1);
}

__global__ void dinv_fin(const int* __restrict__ deg, float* dinv, int n) {
    int i = blockIdx.x * blockDim.x + threadIdx.x;
    if (i < n) dinv[i] = rsqrtf((float)(deg[i] + 1));   // +1 self-loop
}

__global__ __launch_bounds__(512) void scan1(const int* __restrict__ deg, int* blockSums, int n) {
    __shared__ int sm[512];
    int t = threadIdx.x;
    int i = blockIdx.x * 512 + t;
    sm[t] = (i < n) ? deg[i] : 0;
    __syncthreads();
    for (int o = 256; o > 0; o >>= 1) {
        if (t < o) sm[t] += sm[t + o];
        __syncthreads();
    }
    if (t == 0) blockSums[blockIdx.x] = sm[0];
}

__global__ __launch_bounds__(256) void scan2(int* blockSums, int nb) {
    __shared__ int sm[256];
    int t = threadIdx.x;
    int v = (t < nb) ? blockSums[t] : 0;
    sm[t] = v;
    __syncthreads();
    for (int o = 1; o < 256; o <<= 1) {
        int x = (t >= o) ? sm[t - o] : 0;
        __syncthreads();
        sm[t] += x;
        __syncthreads();
    }
    if (t < nb) blockSums[t] = sm[t] - v;   // exclusive
}

__global__ __launch_bounds__(512) void scan3(const int* __restrict__ deg,
                                             const int* __restrict__ blockSums,
                                             int* rowptr, int* cursor, int n) {
    __shared__ int sm[512];
    int t = threadIdx.x;
    int i = blockIdx.x * 512 + t;
    int v = (i < n) ? deg[i] : 0;
    sm[t] = v;
    __syncthreads();
    for (int o = 1; o < 512; o <<= 1) {
        int x = (t >= o) ? sm[t - o] : 0;
        __syncthreads();
        sm[t] += x;
        __syncthreads();
    }
    if (i < n) {
        int r = blockSums[blockIdx.x] + sm[t] - v;   // exclusive
        rowptr[i] = r;
        cursor[i] = r;
    }
}

__global__ void fill_adj(const int* __restrict__ src, const int* __restrict__ dst,
                         int* cursor, int* adj, int e) {
    int i = blockIdx.x * blockDim.x + threadIdx.x;
    if (i < e) {
        int pos = atomicAdd(&cursor[dst[i]], 1);
        adj[pos] = src[i];
    }
}

// ---------------- pipelined GEMM: G[n,NC] = dinv[row] * (A[n,128] @ W[128,NC]) ----------------
// BM=128, BN=NC, BK=16, 256 threads, 8x8 micro-tile, 2-stage cp.async pipeline.
// sA stride 28 floats: 112B rows keep cp.async 16B alignment AND 28*i%32 covers
// 8 distinct banks across the micro-tile rows.

template<int NC>
__global__ __launch_bounds__(256, 2) void gemm_pipe(const float* __restrict__ A,
                                                    const float* __restrict__ W,
                                                    const float* __restrict__ dinv,
                                                    float* __restrict__ G, int n) {
    constexpr int NV = NC / 64;
    constexpr int SAS = 28;
    __shared__ float sA[2][128 * SAS];
    __shared__ float sW[2][16 * NC];

    int tid = threadIdx.x;
    int tx = tid & 15, ty = tid >> 4;
    int row0 = blockIdx.x * 128;

    uint32_t aBase = smem_u32(sA);
    uint32_t wBase = smem_u32(sW);

    float acc[8][4 * NV];
#pragma unroll
    for (int i = 0; i < 8; i++)
#pragma unroll
        for (int j = 0; j < 4 * NV; j++) acc[i][j] = 0.0f;

    // prefetch helper (expanded inline per stage)
#define LOAD_TILE(buf, k0)                                                              \
    {                                                                                   \
        _Pragma("unroll")                                                               \
        for (int p = 0; p < 2; p++) {                                                   \
            int idx = tid + p * 256;                                                    \
            int r = idx >> 2;                                                           \
            int kk4 = (idx & 3) * 4;                                                    \
            int gr = row0 + r;                                                          \
            const float* srcp_ = &A[(long)min(gr, n - 1) * 128 + (k0) + kk4];           \
            int sz = (gr < n) ? 16 : 0;                                                 \
            uint32_t dst = aBase + (uint32_t)(((buf) * 128 * SAS) + r * SAS + kk4) * 4; \
            asm volatile("cp.async.ca.shared.global [%0], [%1], 16, %2;"                \
                         :: "r"(dst), "l"(srcp_), "r"(sz));                             \
        }                                                                               \
        _Pragma("unroll")                                                               \
        for (int q = 0; q < NC / 64; q++) {                                             \
            int idx = tid + q * 256;                                                    \
            int kk = idx / (NC / 4), c4 = idx % (NC / 4);                               \
            const float* srcw_ = &W[(long)((k0) + kk) * NC + c4 * 4];                   \
            uint32_t dst = wBase + (uint32_t)(((buf) * 16 * NC) + kk * NC + c4 * 4) * 4;\
            asm volatile("cp.async.ca.shared.global [%0], [%1], 16;"                    \
                         :: "r"(dst), "l"(srcw_));                                      \
        }                                                                               \
        asm volatile("cp.async.commit_group;");                                        \
    }

    LOAD_TILE(0, 0);

#pragma unroll
    for (int t8 = 0; t8 < 8; t8++) {
        if (t8 < 7) {
            LOAD_TILE((t8 + 1) & 1, (t8 + 1) * 16);
            asm volatile("cp.async.wait_group 1;");
        } else {
            asm volatile("cp.async.wait_group 0;");
        }
        __syncthreads();

        const float* cA = sA[t8 & 1];
        const float* cW = sW[t8 & 1];
#pragma unroll
        for (int kk = 0; kk < 16; kk++) {
            float a[8];
#pragma unroll
            for (int i = 0; i < 8; i++) a[i] = cA[(ty * 8 + i) * SAS + kk];
#pragma unroll
            for (int v = 0; v < NV; v++) {
                float4 b = *reinterpret_cast<const float4*>(&cW[kk * NC + v * 64 + tx * 4]);
#pragma unroll
                for (int i = 0; i < 8; i++) {
                    acc[i][v * 4 + 0] = fmaf(a[i], b.x, acc[i][v * 4 + 0]);
                    acc[i][v * 4 + 1] = fmaf(a[i], b.y, acc[i][v * 4 + 1]);
                    acc[i][v * 4 + 2] = fmaf(a[i], b.z, acc[i][v * 4 + 2]);
                    acc[i][v * 4 + 3] = fmaf(a[i], b.w, acc[i][v * 4 + 3]);
                }
            }
        }
        __syncthreads();
    }
#undef LOAD_TILE

#pragma unroll
    for (int i = 0; i < 8; i++) {
        int gr = row0 + ty * 8 + i;
        if (gr < n) {
            float sc = __ldg(&dinv[gr]);
#pragma unroll
            for (int v = 0; v < NV; v++) {
                float4 r = make_float4(acc[i][v * 4 + 0] * sc, acc[i][v * 4 + 1] * sc,
                                       acc[i][v * 4 + 2] * sc, acc[i][v * 4 + 3] * sc);
                *reinterpret_cast<float4*>(&G[gr * NC + v * 64 + tx * 4]) = r;
            }
        }
    }
}

// ---------------- gather aggregate: OUT[d] = act(dinv[d]*(G[d] + sum G[src]) + b) ----------------
// one warp per dst node; x4 unroll (measured optimum); RELUOUT folds next layer's relu

template<int F, bool RELUOUT>
__global__ __launch_bounds__(256) void gather_k(const float* __restrict__ G,
                                                const int* __restrict__ adj,
                                                const int* __restrict__ rowptr,
                                                const int* __restrict__ deg,
                                                const float* __restrict__ dinv,
                                                const float* __restrict__ b,
                                                float* __restrict__ OUT, int n) {
    int gw = (blockIdx.x * blockDim.x + threadIdx.x) >> 5;
    int lane = threadIdx.x & 31;
    if (gw >= n) return;

    int start = rowptr[gw];
    int cnt = deg[gw];

    if (F == 128) {
        float4 acc = reinterpret_cast<const float4*>(G + (long)gw * F)[lane];
        for (int c = 0; c < cnt; c += 32) {
            int my = 0;
            if (c + lane < cnt) my = __ldg(&adj[start + c + lane]);
            int mend = min(32, cnt - c);
            int m = 0;
            for (; m + 4 <= mend; m += 4) {
                int s0 = __shfl_sync(0xffffffffu, my, m + 0);
                int s1 = __shfl_sync(0xffffffffu, my, m + 1);
                int s2 = __shfl_sync(0xffffffffu, my, m + 2);
                int s3 = __shfl_sync(0xffffffffu, my, m + 3);
                float4 v0 = reinterpret_cast<const float4*>(G + (long)s0 * F)[lane];
                float4 v1 = reinterpret_cast<const float4*>(G + (long)s1 * F)[lane];
                float4 v2 = reinterpret_cast<const float4*>(G + (long)s2 * F)[lane];
                float4 v3 = reinterpret_cast<const float4*>(G + (long)s3 * F)[lane];
                acc.x += v0.x + v1.x + v2.x + v3.x;
                acc.y += v0.y + v1.y + v2.y + v3.y;
                acc.z += v0.z + v1.z + v2.z + v3.z;
                acc.w += v0.w + v1.w + v2.w + v3.w;
            }
            for (; m < mend; m++) {
                int s = __shfl_sync(0xffffffffu, my, m);
                float4 v = reinterpret_cast<const float4*>(G + (long)s * F)[lane];
                acc.x += v.x; acc.y += v.y; acc.z += v.z; acc.w += v.w;
            }
        }
        float sc = dinv[gw];
        float4 bb = reinterpret_cast<const float4*>(b)[lane];
        float4 r;
        r.x = fmaf(acc.x, sc, bb.x);
        r.y = fmaf(acc.y, sc, bb.y);
        r.z = fmaf(acc.z, sc, bb.z);
        r.w = fmaf(acc.w, sc, bb.w);
        if (RELUOUT) {
            r.x = fmaxf(r.x, 0.f); r.y = fmaxf(r.y, 0.f);
            r.z = fmaxf(r.z, 0.f); r.w = fmaxf(r.w, 0.f);
        }
        reinterpret_cast<float4*>(OUT + (long)gw * F)[lane] = r;
    } else {
        float2 acc = reinterpret_cast<const float2*>(G + (long)gw * F)[lane];
        for (int c = 0; c < cnt; c += 32) {
            int my = 0;
            if (c + lane < cnt) my = __ldg(&adj[start + c + lane]);
            int mend = min(32, cnt - c);
            int m = 0;
            for (; m + 4 <= mend; m += 4) {
                int s0 = __shfl_sync(0xffffffffu, my, m + 0);
                int s1 = __shfl_sync(0xffffffffu, my, m + 1);
                int s2 = __shfl_sync(0xffffffffu, my, m + 2);
                int s3 = __shfl_sync(0xffffffffu, my, m + 3);
                float2 v0 = reinterpret_cast<const float2*>(G + (long)s0 * F)[lane];
                float2 v1 = reinterpret_cast<const float2*>(G + (long)s1 * F)[lane];
                float2 v2 = reinterpret_cast<const float2*>(G + (long)s2 * F)[lane];
                float2 v3 = reinterpret_cast<const float2*>(G + (long)s3 * F)[lane];
                acc.x += v0.x + v1.x + v2.x + v3.x;
                acc.y += v0.y + v1.y + v2.y + v3.y;
            }
            for (; m < mend; m++) {
                int s = __shfl_sync(0xffffffffu, my, m);
                float2 v = reinterpret_cast<const float2*>(G + (long)s * F)[lane];
                acc.x += v.x; acc.y += v.y;
            }
        }
        float sc = dinv[gw];
        float2 bb = reinterpret_cast<const float2*>(b)[lane];
        float2 r;
        r.x = fmaf(acc.x, sc, bb.x);
        r.y = fmaf(acc.y, sc, bb.y);
        if (RELUOUT) {
            r.x = fmaxf(r.x, 0.f); r.y = fmaxf(r.y, 0.f);
        }
        reinterpret_cast<float2*>(OUT + (long)gw * F)[lane] = r;
    }
}

// ---------------- launch ----------------

extern "C" void kernel_launch(void* const* d_in, const int* in_sizes, int n_in,
                              void* d_out, int out_size) {
    const float* x  = (const float*)d_in[0];
    const int*   ei = (const int*)  d_in[1];
    const float* W1 = (const float*)d_in[2];
    const float* b1 = (const float*)d_in[3];
    const float* W2 = (const float*)d_in[4];
    const float* b2 = (const float*)d_in[5];
    const float* W3 = (const float*)d_in[6];
    const float* b3 = (const float*)d_in[7];
    float* out = (float*)d_out;

    int n = in_sizes[0] / FIN;
    int e = in_sizes[1] / 2;
    const int* srcp = ei;
    const int* dstp = ei + e;

    float *dinv, *G, *ACC;
    int *deg, *rowptr, *cursor, *adj, *blockSums;
    cudaGetSymbolAddress((void**)&dinv, g_dinv);
    cudaGetSymbolAddress((void**)&deg,  g_deg);
    cudaGetSymbolAddress((void**)&rowptr, g_rowptr);
    cudaGetSymbolAddress((void**)&cursor, g_cursor);
    cudaGetSymbolAddress((void**)&adj,  g_adj);
    cudaGetSymbolAddress((void**)&blockSums, g_blockSums);
    cudaGetSymbolAddress((void**)&G,    g_G);
    cudaGetSymbolAddress((void**)&ACC,  g_ACC);

    const int T = 256;
    int gN = (n + T - 1) / T;
    int gE = (e + T - 1) / T;
    int gM = (n + 127) / 128;
    int nb = (n + 511) / 512;
    int gW = (n * 32 + T - 1) / T;

    static cudaStream_t s1 = []{ cudaStream_t s; cudaStreamCreateWithFlags(&s, cudaStreamNonBlocking); return s; }();
    static cudaEvent_t evFork = []{ cudaEvent_t ev; cudaEventCreateWithFlags(&ev, cudaEventDisableTiming); return ev; }();
    static cudaEvent_t evJoin = []{ cudaEvent_t ev; cudaEventCreateWithFlags(&ev, cudaEventDisableTiming); return ev; }();

    // ---- serial prefix: degree + dinv ----
    cudaMemsetAsync(deg, 0, n * sizeof(int), 0);
    deg_count<<<gE, T>>>(dstp, deg, e);
    dinv_fin<<<gN, T>>>(deg, dinv, n);

    // ---- fork: scan+fill_adj on s1 || gemm1 on main ----
    cudaEventRecord(evFork, 0);
    cudaStreamWaitEvent(s1, evFork, 0);

    scan1<<<nb, 512, 0, s1>>>(deg, blockSums, n);
    scan2<<<1, 256, 0, s1>>>(blockSums, nb);
    scan3<<<nb, 512, 0, s1>>>(deg, blockSums, rowptr, cursor, n);
    fill_adj<<<gE, T, 0, s1>>>(srcp, dstp, cursor, adj, e);
    cudaEventRecord(evJoin, s1);

    gemm_pipe<FHID><<<gM, T>>>(x, W1, dinv, G, n);   // concurrent with s1

    cudaStreamWaitEvent(0, evJoin, 0);

    // layer 1 gather (+relu for layer 2 input)
    gather_k<FHID, true><<<gW, T>>>(G, adj, rowptr, deg, dinv, b1, ACC, n);

    // layer 2 (A already relu'd)
    gemm_pipe<FHID><<<gM, T>>>(ACC, W2, dinv, G, n);
    gather_k<FHID, true><<<gW, T>>>(G, adj, rowptr, deg, dinv, b2, ACC, n);

    // layer 3 (no relu on output)
    gemm_pipe<FOUT><<<gM, T>>>(ACC, W3, dinv, G, n);
    gather_k<FOUT, false><<<gW, T>>>(G, adj, rowptr, deg, dinv, b3, out, n);
}

// round 10
// speedup vs baseline: 1.0166x; 1.0166x over previous
#include <cuda_runtime.h>
#include <cstdint>

#define NNODES 100000
#define NEDGES 1600000
#define FIN  128
#define FHID 128
#define FOUT 64

// Scratch (allocation-free rule: __device__ globals)
__device__ float g_dinv[NNODES];
__device__ int   g_deg [NNODES];
__device__ int   g_rowptr[NNODES];
__device__ int   g_cursor[NNODES];
__device__ int   g_adj [NEDGES];
__device__ int   g_blockSums[256];
__device__ float g_G  [NNODES * FHID];   // pre-scaled GEMM output (dinv[v]*h_v)
__device__ float g_ACC[NNODES * FHID];   // aggregated output / next-layer input

// ---------------- degree / norm / CSR build ----------------

__global__ void deg_count(const int* __restrict__ dst, int* deg, int e) {
    int i = blockIdx.x * blockDim.x + threadIdx.x;
    if (i < e) atomicAdd(&deg[dst[i]], 1);
}

__global__ void dinv_fin(const int* __restrict__ deg, float* dinv, int n) {
    int i = blockIdx.x * blockDim.x + threadIdx.x;
    if (i < n) dinv[i] = rsqrtf((float)(deg[i] + 1));   // +1 self-loop
}

__global__ __launch_bounds__(512) void scan1(const int* __restrict__ deg, int* blockSums, int n) {
    __shared__ int sm[512];
    int t = threadIdx.x;
    int i = blockIdx.x * 512 + t;
    sm[t] = (i < n) ? deg[i] : 0;
    __syncthreads();
    for (int o = 256; o > 0; o >>= 1) {
        if (t < o) sm[t] += sm[t + o];
        __syncthreads();
    }
    if (t == 0) blockSums[blockIdx.x] = sm[0];
}

// scan3f: fuses the blockSums scan (old scan2) into every block (redundant but
// cheap: 196 values in smem) + per-block exclusive scan -> rowptr & cursor.
__global__ __launch_bounds__(512) void scan3f(const int* __restrict__ deg,
                                              const int* __restrict__ blockSums,
                                              int* rowptr, int* cursor, int n, int nb) {
    __shared__ int sb[256];
    __shared__ int sm[512];
    int t = threadIdx.x;

    // inclusive scan of blockSums (nb <= 256) using first 256 threads
    if (t < 256) sb[t] = (t < nb) ? blockSums[t] : 0;
    __syncthreads();
    for (int o = 1; o < 256; o <<= 1) {
        int x = (t < 256 && t >= o) ? sb[t - o] : 0;
        __syncthreads();
        if (t < 256) sb[t] += x;
        __syncthreads();
    }
    int blockOffset = (blockIdx.x > 0) ? sb[blockIdx.x - 1] : 0;

    int i = blockIdx.x * 512 + t;
    int v = (i < n) ? deg[i] : 0;
    sm[t] = v;
    __syncthreads();
    for (int o = 1; o < 512; o <<= 1) {
        int x = (t >= o) ? sm[t - o] : 0;
        __syncthreads();
        sm[t] += x;
        __syncthreads();
    }
    if (i < n) {
        int r = blockOffset + sm[t] - v;   // exclusive
        rowptr[i] = r;
        cursor[i] = r;
    }
}

__global__ void fill_adj(const int* __restrict__ src, const int* __restrict__ dst,
                         int* cursor, int* adj, int e) {
    int i = blockIdx.x * blockDim.x + threadIdx.x;
    if (i < e) {
        int pos = atomicAdd(&cursor[dst[i]], 1);
        adj[pos] = src[i];
    }
}

// ---------------- GEMM: G[n,NC] = dinv[row] * ((relu?)A[n,128] @ W[128,NC]) ----------------
// Tile: BM=128, BN=NC, BK=16. 256 threads (tx 0..15, ty 0..15).
// Micro-tile: 8 rows (ty*8) x 8 cols as NV float4 groups at {v*64 + tx*4}.

template<int NC, bool RELU>
__global__ __launch_bounds__(256, 2) void gemm_k(const float* __restrict__ A,
                                                 const float* __restrict__ W,
                                                 const float* __restrict__ dinv,
                                                 float* __restrict__ G, int n) {
    constexpr int NV = NC / 64;   // float4 col-groups per thread (2 for 128, 1 for 64)
    __shared__ float sA[128][20];
    __shared__ float sW[16][NC];

    int tid = threadIdx.x;
    int tx = tid & 15, ty = tid >> 4;
    int row0 = blockIdx.x * 128;

    float acc[8][4 * NV];
#pragma unroll
    for (int i = 0; i < 8; i++)
#pragma unroll
        for (int j = 0; j < 4 * NV; j++) acc[i][j] = 0.0f;

#pragma unroll 1
    for (int k0 = 0; k0 < 128; k0 += 16) {
#pragma unroll
        for (int p = 0; p < 2; p++) {
            int r = p * 64 + (tid >> 2);
            int kk4 = (tid & 3) * 4;
            int gr = row0 + r;
            float4 v = make_float4(0.f, 0.f, 0.f, 0.f);
            if (gr < n) v = *reinterpret_cast<const float4*>(&A[gr * 128 + k0 + kk4]);
            if (RELU) {
                v.x = fmaxf(v.x, 0.f); v.y = fmaxf(v.y, 0.f);
                v.z = fmaxf(v.z, 0.f); v.w = fmaxf(v.w, 0.f);
            }
            sA[r][kk4 + 0] = v.x; sA[r][kk4 + 1] = v.y;
            sA[r][kk4 + 2] = v.z; sA[r][kk4 + 3] = v.w;
        }
#pragma unroll
        for (int q = 0; q < NC / 64; q++) {
            int l = tid + q * 256;
            int kk = l / (NC / 4), c4 = l % (NC / 4);
            *reinterpret_cast<float4*>(&sW[kk][c4 * 4]) =
                *reinterpret_cast<const float4*>(&W[(k0 + kk) * NC + c4 * 4]);
        }
        __syncthreads();

#pragma unroll
        for (int kk = 0; kk < 16; kk++) {
            float a[8];
#pragma unroll
            for (int i = 0; i < 8; i++) a[i] = sA[ty * 8 + i][kk];
#pragma unroll
            for (int v = 0; v < NV; v++) {
                float4 b = *reinterpret_cast<const float4*>(&sW[kk][v * 64 + tx * 4]);
#pragma unroll
                for (int i = 0; i < 8; i++) {
                    acc[i][v * 4 + 0] = fmaf(a[i], b.x, acc[i][v * 4 + 0]);
                    acc[i][v * 4 + 1] = fmaf(a[i], b.y, acc[i][v * 4 + 1]);
                    acc[i][v * 4 + 2] = fmaf(a[i], b.z, acc[i][v * 4 + 2]);
                    acc[i][v * 4 + 3] = fmaf(a[i], b.w, acc[i][v * 4 + 3]);
                }
            }
        }
        __syncthreads();
    }

#pragma unroll
    for (int i = 0; i < 8; i++) {
        int gr = row0 + ty * 8 + i;
        if (gr < n) {
            float sc = __ldg(&dinv[gr]);
#pragma unroll
            for (int v = 0; v < NV; v++) {
                float4 r = make_float4(acc[i][v * 4 + 0] * sc, acc[i][v * 4 + 1] * sc,
                                       acc[i][v * 4 + 2] * sc, acc[i][v * 4 + 3] * sc);
                *reinterpret_cast<float4*>(&G[gr * NC + v * 64 + tx * 4]) = r;
            }
        }
    }
}

// ---------------- gather aggregate: OUT[d] = dinv[d]*(G[d] + sum_{src in N(d)} G[src]) + b ----------------
// one warp per dst node; neighbor loop unrolled x4 for MLP (measured optimum)

template<int F>
__global__ __launch_bounds__(256) void gather_k(const float* __restrict__ G,
                                                const int* __restrict__ adj,
                                                const int* __restrict__ rowptr,
                                                const int* __restrict__ deg,
                                                const float* __restrict__ dinv,
                                                const float* __restrict__ b,
                                                float* __restrict__ OUT, int n) {
    int gw = (blockIdx.x * blockDim.x + threadIdx.x) >> 5;
    int lane = threadIdx.x & 31;
    if (gw >= n) return;

    int start = rowptr[gw];
    int cnt = deg[gw];

    if (F == 128) {
        float4 acc = reinterpret_cast<const float4*>(G + (long)gw * F)[lane];
        for (int c = 0; c < cnt; c += 32) {
            int my = 0;
            if (c + lane < cnt) my = __ldg(&adj[start + c + lane]);
            int mend = min(32, cnt - c);
            int m = 0;
            for (; m + 4 <= mend; m += 4) {
                int s0 = __shfl_sync(0xffffffffu, my, m + 0);
                int s1 = __shfl_sync(0xffffffffu, my, m + 1);
                int s2 = __shfl_sync(0xffffffffu, my, m + 2);
                int s3 = __shfl_sync(0xffffffffu, my, m + 3);
                float4 v0 = reinterpret_cast<const float4*>(G + (long)s0 * F)[lane];
                float4 v1 = reinterpret_cast<const float4*>(G + (long)s1 * F)[lane];
                float4 v2 = reinterpret_cast<const float4*>(G + (long)s2 * F)[lane];
                float4 v3 = reinterpret_cast<const float4*>(G + (long)s3 * F)[lane];
                acc.x += v0.x + v1.x + v2.x + v3.x;
                acc.y += v0.y + v1.y + v2.y + v3.y;
                acc.z += v0.z + v1.z + v2.z + v3.z;
                acc.w += v0.w + v1.w + v2.w + v3.w;
            }
            for (; m < mend; m++) {
                int s = __shfl_sync(0xffffffffu, my, m);
                float4 v = reinterpret_cast<const float4*>(G + (long)s * F)[lane];
                acc.x += v.x; acc.y += v.y; acc.z += v.z; acc.w += v.w;
            }
        }
        float sc = dinv[gw];
        float4 bb = reinterpret_cast<const float4*>(b)[lane];
        float4 r;
        r.x = fmaf(acc.x, sc, bb.x);
        r.y = fmaf(acc.y, sc, bb.y);
        r.z = fmaf(acc.z, sc, bb.z);
        r.w = fmaf(acc.w, sc, bb.w);
        reinterpret_cast<float4*>(OUT + (long)gw * F)[lane] = r;
    } else {
        float2 acc = reinterpret_cast<const float2*>(G + (long)gw * F)[lane];
        for (int c = 0; c < cnt; c += 32) {
            int my = 0;
            if (c + lane < cnt) my = __ldg(&adj[start + c + lane]);
            int mend = min(32, cnt - c);
            int m = 0;
            for (; m + 4 <= mend; m += 4) {
                int s0 = __shfl_sync(0xffffffffu, my, m + 0);
                int s1 = __shfl_sync(0xffffffffu, my, m + 1);
                int s2 = __shfl_sync(0xffffffffu, my, m + 2);
                int s3 = __shfl_sync(0xffffffffu, my, m + 3);
                float2 v0 = reinterpret_cast<const float2*>(G + (long)s0 * F)[lane];
                float2 v1 = reinterpret_cast<const float2*>(G + (long)s1 * F)[lane];
                float2 v2 = reinterpret_cast<const float2*>(G + (long)s2 * F)[lane];
                float2 v3 = reinterpret_cast<const float2*>(G + (long)s3 * F)[lane];
                acc.x += v0.x + v1.x + v2.x + v3.x;
                acc.y += v0.y + v1.y + v2.y + v3.y;
            }
            for (; m < mend; m++) {
                int s = __shfl_sync(0xffffffffu, my, m);
                float2 v = reinterpret_cast<const float2*>(G + (long)s * F)[lane];
                acc.x += v.x; acc.y += v.y;
            }
        }
        float sc = dinv[gw];
        float2 bb = reinterpret_cast<const float2*>(b)[lane];
        float2 r;
        r.x = fmaf(acc.x, sc, bb.x);
        r.y = fmaf(acc.y, sc, bb.y);
        reinterpret_cast<float2*>(OUT + (long)gw * F)[lane] = r;
    }
}

// ---------------- launch ----------------

extern "C" void kernel_launch(void* const* d_in, const int* in_sizes, int n_in,
                              void* d_out, int out_size) {
    const float* x  = (const float*)d_in[0];
    const int*   ei = (const int*)  d_in[1];
    const float* W1 = (const float*)d_in[2];
    const float* b1 = (const float*)d_in[3];
    const float* W2 = (const float*)d_in[4];
    const float* b2 = (const float*)d_in[5];
    const float* W3 = (const float*)d_in[6];
    const float* b3 = (const float*)d_in[7];
    float* out = (float*)d_out;

    int n = in_sizes[0] / FIN;
    int e = in_sizes[1] / 2;
    const int* srcp = ei;
    const int* dstp = ei + e;

    float *dinv, *G, *ACC;
    int *deg, *rowptr, *cursor, *adj, *blockSums;
    cudaGetSymbolAddress((void**)&dinv, g_dinv);
    cudaGetSymbolAddress((void**)&deg,  g_deg);
    cudaGetSymbolAddress((void**)&rowptr, g_rowptr);
    cudaGetSymbolAddress((void**)&cursor, g_cursor);
    cudaGetSymbolAddress((void**)&adj,  g_adj);
    cudaGetSymbolAddress((void**)&blockSums, g_blockSums);
    cudaGetSymbolAddress((void**)&G,    g_G);
    cudaGetSymbolAddress((void**)&ACC,  g_ACC);

    const int T = 256;
    int gN = (n + T - 1) / T;
    int gE = (e + T - 1) / T;
    int gM = (n + 127) / 128;            // 128-row GEMM tiles
    int nb = (n + 511) / 512;
    int gW = (n * 32 + T - 1) / T;       // warp-per-node grids

    static cudaStream_t s1 = []{ cudaStream_t s; cudaStreamCreateWithFlags(&s, cudaStreamNonBlocking); return s; }();
    static cudaEvent_t evFork = []{ cudaEvent_t ev; cudaEventCreateWithFlags(&ev, cudaEventDisableTiming); return ev; }();
    static cudaEvent_t evJoin = []{ cudaEvent_t ev; cudaEventCreateWithFlags(&ev, cudaEventDisableTiming); return ev; }();

    // ---- serial prefix: degree + dinv (needed by gemm1 AND scan chain) ----
    cudaMemsetAsync(deg, 0, n * sizeof(int), 0);
    deg_count<<<gE, T>>>(dstp, deg, e);
    dinv_fin<<<gN, T>>>(deg, dinv, n);

    // ---- fork: scan+fill_adj on s1 || gemm1 on main ----
    cudaEventRecord(evFork, 0);
    cudaStreamWaitEvent(s1, evFork, 0);

    scan1<<<nb, 512, 0, s1>>>(deg, blockSums, n);
    scan3f<<<nb, 512, 0, s1>>>(deg, blockSums, rowptr, cursor, n, nb);
    fill_adj<<<gE, T, 0, s1>>>(srcp, dstp, cursor, adj, e);
    cudaEventRecord(evJoin, s1);

    gemm_k<FHID, false><<<gM, T>>>(x, W1, dinv, G, n);   // main, concurrent with s1

    // ---- join: gather needs adj/rowptr ----
    cudaStreamWaitEvent(0, evJoin, 0);

    gather_k<FHID><<<gW, T>>>(G, adj, rowptr, deg, dinv, b1, ACC, n);

    // ---- layer 2 ----
    gemm_k<FHID, true><<<gM, T>>>(ACC, W2, dinv, G, n);
    gather_k<FHID><<<gW, T>>>(G, adj, rowptr, deg, dinv, b2, ACC, n);

    // ---- layer 3 ----
    gemm_k<FOUT, true><<<gM, T>>>(ACC, W3, dinv, G, n);
    gather_k<FOUT><<<gW, T>>>(G, adj, rowptr, deg, dinv, b3, out, n);
}

// round 11
// speedup vs baseline: 1.4079x; 1.3849x over previous
#include <cuda_runtime.h>
#include <cuda_bf16.h>
#include <cstdint>

#define NNODES 100000
#define NEDGES 1600000
#define FIN  128
#define FHID 128
#define FOUT 64

// Scratch (allocation-free rule: __device__ globals)
__device__ float g_dinv[NNODES];
__device__ int   g_deg [NNODES];
__device__ int   g_rowptr[NNODES];
__device__ int   g_cursor[NNODES];
__device__ int   g_adj [NEDGES];
__device__ int   g_blockSums[256];
__device__ float g_G  [NNODES * FHID];
__device__ float g_ACC[NNODES * FHID];

// ---------------- helpers ----------------

__device__ __forceinline__ uint32_t smem_u32(const void* p) {
    uint32_t a;
    asm("{ .reg .u64 t; cvta.to.shared.u64 t, %1; cvt.u32.u64 %0, t; }" : "=r"(a) : "l"(p));
    return a;
}

__device__ __forceinline__ void ldm_x4(uint32_t* r, uint32_t addr) {
    asm volatile("ldmatrix.sync.aligned.m8n8.x4.shared.b16 {%0,%1,%2,%3}, [%4];"
                 : "=r"(r[0]), "=r"(r[1]), "=r"(r[2]), "=r"(r[3]) : "r"(addr));
}

__device__ __forceinline__ void ldm_x4t(uint32_t* r, uint32_t addr) {
    asm volatile("ldmatrix.sync.aligned.m8n8.x4.trans.shared.b16 {%0,%1,%2,%3}, [%4];"
                 : "=r"(r[0]), "=r"(r[1]), "=r"(r[2]), "=r"(r[3]) : "r"(addr));
}

__device__ __forceinline__ void mma16816(float* c, const uint32_t* a,
                                         uint32_t b0, uint32_t b1) {
    asm volatile("mma.sync.aligned.m16n8k16.row.col.f32.bf16.bf16.f32 "
                 "{%0,%1,%2,%3}, {%4,%5,%6,%7}, {%8,%9}, {%0,%1,%2,%3};"
                 : "+f"(c[0]), "+f"(c[1]), "+f"(c[2]), "+f"(c[3])
                 : "r"(a[0]), "r"(a[1]), "r"(a[2]), "r"(a[3]), "r"(b0), "r"(b1));
}

__device__ __forceinline__ uint32_t pack_hi(float x, float y, float& rx, float& ry) {
    __nv_bfloat16 hx = __float2bfloat16_rn(x);
    __nv_bfloat16 hy = __float2bfloat16_rn(y);
    rx = x - __bfloat162float(hx);
    ry = y - __bfloat162float(hy);
    __nv_bfloat162 h(hx, hy);
    return *reinterpret_cast<uint32_t*>(&h);
}

__device__ __forceinline__ uint32_t pack_lo(float rx, float ry) {
    __nv_bfloat162 l = __floats2bfloat162_rn(rx, ry);
    return *reinterpret_cast<uint32_t*>(&l);
}

// ---------------- degree / norm / CSR build ----------------

__global__ void deg_count(const int* __restrict__ dst, int* deg, int e) {
    int i = blockIdx.x * blockDim.x + threadIdx.x;
    if (i < e) atomicAdd(&deg[dst[i]], 1);
}

__global__ void dinv_fin(const int* __restrict__ deg, float* dinv, int n) {
    int i = blockIdx.x * blockDim.x + threadIdx.x;
    if (i < n) dinv[i] = rsqrtf((float)(deg[i] + 1));
}

__global__ __launch_bounds__(512) void scan1(const int* __restrict__ deg, int* blockSums, int n) {
    __shared__ int sm[512];
    int t = threadIdx.x;
    int i = blockIdx.x * 512 + t;
    sm[t] = (i < n) ? deg[i] : 0;
    __syncthreads();
    for (int o = 256; o > 0; o >>= 1) {
        if (t < o) sm[t] += sm[t + o];
        __syncthreads();
    }
    if (t == 0) blockSums[blockIdx.x] = sm[0];
}

__global__ __launch_bounds__(512) void scan3f(const int* __restrict__ deg,
                                              const int* __restrict__ blockSums,
                                              int* rowptr, int* cursor, int n, int nb) {
    __shared__ int sb[256];
    __shared__ int sm[512];
    int t = threadIdx.x;
    if (t < 256) sb[t] = (t < nb) ? blockSums[t] : 0;
    __syncthreads();
    for (int o = 1; o < 256; o <<= 1) {
        int x = (t < 256 && t >= o) ? sb[t - o] : 0;
        __syncthreads();
        if (t < 256) sb[t] += x;
        __syncthreads();
    }
    int blockOffset = (blockIdx.x > 0) ? sb[blockIdx.x - 1] : 0;

    int i = blockIdx.x * 512 + t;
    int v = (i < n) ? deg[i] : 0;
    sm[t] = v;
    __syncthreads();
    for (int o = 1; o < 512; o <<= 1) {
        int x = (t >= o) ? sm[t - o] : 0;
        __syncthreads();
        sm[t] += x;
        __syncthreads();
    }
    if (i < n) {
        int r = blockOffset + sm[t] - v;
        rowptr[i] = r;
        cursor[i] = r;
    }
}

__global__ void fill_adj(const int* __restrict__ src, const int* __restrict__ dst,
                         int* cursor, int* adj, int e) {
    int i = blockIdx.x * blockDim.x + threadIdx.x;
    if (i < e) {
        int pos = atomicAdd(&cursor[dst[i]], 1);
        adj[pos] = src[i];
    }
}

// ---------------- split-bf16 HMMA GEMM v2 ----------------
// G[n,NC] = dinv[row] * ((relu?)A[n,128] @ W[128,NC])
// CTA: 128 rows x NC, 256 threads (8 warps: wm = wid&3 -> 32 rows, wn = wid>>2 -> NC/2 cols).
// K processed in 4 chunks of 32. A in smem [m][k] (stride 40), B k-major [k][n] (stride NC+8)
// -> both fills vectorized (uint2), B frags via ldmatrix.x4.trans. 3-pass split accumulate.

template<int NC, bool RELU>
__global__ __launch_bounds__(256, 2) void gemm_hmma(const float* __restrict__ A,
                                                    const float* __restrict__ W,
                                                    const float* __restrict__ dinv,
                                                    float* __restrict__ G, int n) {
    constexpr int SKA = 40;          // sA k-stride (elems)
    constexpr int SNB = NC + 8;      // sB n-stride (elems)
    constexpr int NTW = NC / 16;     // n-tiles per warp (8 / 4)
    constexpr int NP  = NTW / 2;     // ldm x4.trans pairs

    __shared__ __nv_bfloat16 sAh[128 * SKA];
    __shared__ __nv_bfloat16 sAl[128 * SKA];
    __shared__ __nv_bfloat16 sBh[32 * SNB];
    __shared__ __nv_bfloat16 sBl[32 * SNB];

    int tid = threadIdx.x;
    int wid = tid >> 5;
    int lane = tid & 31;
    int wm = wid & 3;
    int wn = wid >> 2;
    int row0 = blockIdx.x * 128;

    uint32_t bAh = smem_u32(sAh), bAl = smem_u32(sAl);
    uint32_t bBh = smem_u32(sBh), bBl = smem_u32(sBl);

    float acc[2][NTW][4];
#pragma unroll
    for (int mt = 0; mt < 2; mt++)
#pragma unroll
        for (int t = 0; t < NTW; t++)
#pragma unroll
            for (int j = 0; j < 4; j++) acc[mt][t][j] = 0.f;

#pragma unroll 1
    for (int ch = 0; ch < 4; ch++) {
        int k0c = ch * 32;

        // ---- fill A: 128 x 32, 4 float4 per thread ----
#pragma unroll
        for (int j = 0; j < 4; j++) {
            int s = tid + j * 256;
            int row = s >> 3;
            int kg = s & 7;
            int gr = row0 + row;
            float4 v = make_float4(0.f, 0.f, 0.f, 0.f);
            if (gr < n) v = *reinterpret_cast<const float4*>(&A[(long)gr * 128 + k0c + kg * 4]);
            if (RELU) {
                v.x = fmaxf(v.x, 0.f); v.y = fmaxf(v.y, 0.f);
                v.z = fmaxf(v.z, 0.f); v.w = fmaxf(v.w, 0.f);
            }
            float rx, ry, rz, rw;
            uint2 h, l;
            h.x = pack_hi(v.x, v.y, rx, ry);
            h.y = pack_hi(v.z, v.w, rz, rw);
            l.x = pack_lo(rx, ry);
            l.y = pack_lo(rz, rw);
            *reinterpret_cast<uint2*>(&sAh[row * SKA + kg * 4]) = h;
            *reinterpret_cast<uint2*>(&sAl[row * SKA + kg * 4]) = l;
        }

        // ---- fill B: 32 x NC (k-major, same as W) ----
#pragma unroll
        for (int j = 0; j < NC / 32; j++) {
            int s = tid + j * 256;
            int krow = s / (NC / 4);
            int ng = s % (NC / 4);
            float4 v = *reinterpret_cast<const float4*>(&W[(long)(k0c + krow) * NC + ng * 4]);
            float rx, ry, rz, rw;
            uint2 h, l;
            h.x = pack_hi(v.x, v.y, rx, ry);
            h.y = pack_hi(v.z, v.w, rz, rw);
            l.x = pack_lo(rx, ry);
            l.y = pack_lo(rz, rw);
            *reinterpret_cast<uint2*>(&sBh[krow * SNB + ng * 4]) = h;
            *reinterpret_cast<uint2*>(&sBl[krow * SNB + ng * 4]) = l;
        }
        __syncthreads();

        // ---- compute: 2 k-steps of 16 ----
#pragma unroll
        for (int ks = 0; ks < 2; ks++) {
            // A fragments (2 m-tiles, hi+lo)
            uint32_t aH[2][4], aL[2][4];
            int lrow = lane & 15;
            int lk = ks * 16 + ((lane >> 4) & 1) * 8;
#pragma unroll
            for (int mt = 0; mt < 2; mt++) {
                uint32_t off = (uint32_t)((wm * 32 + mt * 16 + lrow) * SKA + lk) * 2;
                ldm_x4(aH[mt], bAh + off);
                ldm_x4(aL[mt], bAl + off);
            }

#pragma unroll
            for (int np = 0; np < NP; np++) {
                int n0 = wn * (NC / 2) + np * 16;
                int kr = ks * 16 + (lane & 15);
                int ncol = n0 + ((lane >> 4) & 1) * 8;
                uint32_t boff = (uint32_t)(kr * SNB + ncol) * 2;
                uint32_t bH[4], bL[4];
                ldm_x4t(bH, bBh + boff);
                ldm_x4t(bL, bBl + boff);
#pragma unroll
                for (int h = 0; h < 2; h++) {
                    int t = np * 2 + h;
#pragma unroll
                    for (int mt = 0; mt < 2; mt++) {
                        mma16816(acc[mt][t], aH[mt], bH[2 * h], bH[2 * h + 1]);
                        mma16816(acc[mt][t], aL[mt], bH[2 * h], bH[2 * h + 1]);
                        mma16816(acc[mt][t], aH[mt], bL[2 * h], bL[2 * h + 1]);
                    }
                }
            }
        }
        __syncthreads();
    }

    // ---- epilogue ----
#pragma unroll
    for (int mt = 0; mt < 2; mt++) {
        int r0 = row0 + wm * 32 + mt * 16 + (lane >> 2);
        int r1 = r0 + 8;
        float sc0 = (r0 < n) ? __ldg(&dinv[r0]) : 0.f;
        float sc1 = (r1 < n) ? __ldg(&dinv[r1]) : 0.f;
#pragma unroll
        for (int t = 0; t < NTW; t++) {
            int col = wn * (NC / 2) + t * 8 + (lane & 3) * 2;
            if (r0 < n) {
                float2 o = make_float2(acc[mt][t][0] * sc0, acc[mt][t][1] * sc0);
                *reinterpret_cast<float2*>(&G[(long)r0 * NC + col]) = o;
            }
            if (r1 < n) {
                float2 o = make_float2(acc[mt][t][2] * sc1, acc[mt][t][3] * sc1);
                *reinterpret_cast<float2*>(&G[(long)r1 * NC + col]) = o;
            }
        }
    }
}

// ---------------- gather aggregate (R8-proven: x4 unroll) ----------------

template<int F>
__global__ __launch_bounds__(256) void gather_k(const float* __restrict__ G,
                                                const int* __restrict__ adj,
                                                const int* __restrict__ rowptr,
                                                const int* __restrict__ deg,
                                                const float* __restrict__ dinv,
                                                const float* __restrict__ b,
                                                float* __restrict__ OUT, int n) {
    int gw = (blockIdx.x * blockDim.x + threadIdx.x) >> 5;
    int lane = threadIdx.x & 31;
    if (gw >= n) return;

    int start = rowptr[gw];
    int cnt = deg[gw];

    if (F == 128) {
        float4 acc = reinterpret_cast<const float4*>(G + (long)gw * F)[lane];
        for (int c = 0; c < cnt; c += 32) {
            int my = 0;
            if (c + lane < cnt) my = __ldg(&adj[start + c + lane]);
            int mend = min(32, cnt - c);
            int m = 0;
            for (; m + 4 <= mend; m += 4) {
                int s0 = __shfl_sync(0xffffffffu, my, m + 0);
                int s1 = __shfl_sync(0xffffffffu, my, m + 1);
                int s2 = __shfl_sync(0xffffffffu, my, m + 2);
                int s3 = __shfl_sync(0xffffffffu, my, m + 3);
                float4 v0 = reinterpret_cast<const float4*>(G + (long)s0 * F)[lane];
                float4 v1 = reinterpret_cast<const float4*>(G + (long)s1 * F)[lane];
                float4 v2 = reinterpret_cast<const float4*>(G + (long)s2 * F)[lane];
                float4 v3 = reinterpret_cast<const float4*>(G + (long)s3 * F)[lane];
                acc.x += v0.x + v1.x + v2.x + v3.x;
                acc.y += v0.y + v1.y + v2.y + v3.y;
                acc.z += v0.z + v1.z + v2.z + v3.z;
                acc.w += v0.w + v1.w + v2.w + v3.w;
            }
            for (; m < mend; m++) {
                int s = __shfl_sync(0xffffffffu, my, m);
                float4 v = reinterpret_cast<const float4*>(G + (long)s * F)[lane];
                acc.x += v.x; acc.y += v.y; acc.z += v.z; acc.w += v.w;
            }
        }
        float sc = dinv[gw];
        float4 bb = reinterpret_cast<const float4*>(b)[lane];
        float4 r;
        r.x = fmaf(acc.x, sc, bb.x);
        r.y = fmaf(acc.y, sc, bb.y);
        r.z = fmaf(acc.z, sc, bb.z);
        r.w = fmaf(acc.w, sc, bb.w);
        reinterpret_cast<float4*>(OUT + (long)gw * F)[lane] = r;
    } else {
        float2 acc = reinterpret_cast<const float2*>(G + (long)gw * F)[lane];
        for (int c = 0; c < cnt; c += 32) {
            int my = 0;
            if (c + lane < cnt) my = __ldg(&adj[start + c + lane]);
            int mend = min(32, cnt - c);
            int m = 0;
            for (; m + 4 <= mend; m += 4) {
                int s0 = __shfl_sync(0xffffffffu, my, m + 0);
                int s1 = __shfl_sync(0xffffffffu, my, m + 1);
                int s2 = __shfl_sync(0xffffffffu, my, m + 2);
                int s3 = __shfl_sync(0xffffffffu, my, m + 3);
                float2 v0 = reinterpret_cast<const float2*>(G + (long)s0 * F)[lane];
                float2 v1 = reinterpret_cast<const float2*>(G + (long)s1 * F)[lane];
                float2 v2 = reinterpret_cast<const float2*>(G + (long)s2 * F)[lane];
                float2 v3 = reinterpret_cast<const float2*>(G + (long)s3 * F)[lane];
                acc.x += v0.x + v1.x + v2.x + v3.x;
                acc.y += v0.y + v1.y + v2.y + v3.y;
            }
            for (; m < mend; m++) {
                int s = __shfl_sync(0xffffffffu, my, m);
                float2 v = reinterpret_cast<const float2*>(G + (long)s * F)[lane];
                acc.x += v.x; acc.y += v.y;
            }
        }
        float sc = dinv[gw];
        float2 bb = reinterpret_cast<const float2*>(b)[lane];
        float2 r;
        r.x = fmaf(acc.x, sc, bb.x);
        r.y = fmaf(acc.y, sc, bb.y);
        reinterpret_cast<float2*>(OUT + (long)gw * F)[lane] = r;
    }
}

// ---------------- launch ----------------

extern "C" void kernel_launch(void* const* d_in, const int* in_sizes, int n_in,
                              void* d_out, int out_size) {
    const float* x  = (const float*)d_in[0];
    const int*   ei = (const int*)  d_in[1];
    const float* W1 = (const float*)d_in[2];
    const float* b1 = (const float*)d_in[3];
    const float* W2 = (const float*)d_in[4];
    const float* b2 = (const float*)d_in[5];
    const float* W3 = (const float*)d_in[6];
    const float* b3 = (const float*)d_in[7];
    float* out = (float*)d_out;

    int n = in_sizes[0] / FIN;
    int e = in_sizes[1] / 2;
    const int* srcp = ei;
    const int* dstp = ei + e;

    float *dinv, *G, *ACC;
    int *deg, *rowptr, *cursor, *adj, *blockSums;
    cudaGetSymbolAddress((void**)&dinv, g_dinv);
    cudaGetSymbolAddress((void**)&deg,  g_deg);
    cudaGetSymbolAddress((void**)&rowptr, g_rowptr);
    cudaGetSymbolAddress((void**)&cursor, g_cursor);
    cudaGetSymbolAddress((void**)&adj,  g_adj);
    cudaGetSymbolAddress((void**)&blockSums, g_blockSums);
    cudaGetSymbolAddress((void**)&G,    g_G);
    cudaGetSymbolAddress((void**)&ACC,  g_ACC);

    const int T = 256;
    int gN = (n + T - 1) / T;
    int gE = (e + T - 1) / T;
    int gM = (n + 127) / 128;
    int nb = (n + 511) / 512;
    int gW = (n * 32 + T - 1) / T;

    static cudaStream_t s1 = []{ cudaStream_t s; cudaStreamCreateWithFlags(&s, cudaStreamNonBlocking); return s; }();
    static cudaEvent_t evFork = []{ cudaEvent_t ev; cudaEventCreateWithFlags(&ev, cudaEventDisableTiming); return ev; }();
    static cudaEvent_t evJoin = []{ cudaEvent_t ev; cudaEventCreateWithFlags(&ev, cudaEventDisableTiming); return ev; }();

    // ---- serial prefix: degree + dinv ----
    cudaMemsetAsync(deg, 0, n * sizeof(int), 0);
    deg_count<<<gE, T>>>(dstp, deg, e);
    dinv_fin<<<gN, T>>>(deg, dinv, n);

    // ---- fork: scan+fill_adj on s1 || gemm1 on main ----
    cudaEventRecord(evFork, 0);
    cudaStreamWaitEvent(s1, evFork, 0);

    scan1<<<nb, 512, 0, s1>>>(deg, blockSums, n);
    scan3f<<<nb, 512, 0, s1>>>(deg, blockSums, rowptr, cursor, n, nb);
    fill_adj<<<gE, T, 0, s1>>>(srcp, dstp, cursor, adj, e);
    cudaEventRecord(evJoin, s1);

    gemm_hmma<FHID, false><<<gM, T>>>(x, W1, dinv, G, n);   // concurrent with s1

    cudaStreamWaitEvent(0, evJoin, 0);

    gather_k<FHID><<<gW, T>>>(G, adj, rowptr, deg, dinv, b1, ACC, n);

    gemm_hmma<FHID, true><<<gM, T>>>(ACC, W2, dinv, G, n);
    gather_k<FHID><<<gW, T>>>(G, adj, rowptr, deg, dinv, b2, ACC, n);

    gemm_hmma<FOUT, true><<<gM, T>>>(ACC, W3, dinv, G, n);
    gather_k<FOUT><<<gW, T>>>(G, adj, rowptr, deg, dinv, b3, out, n);
}